// round 1
// baseline (speedup 1.0000x reference)
#include <cuda_runtime.h>
#include <cuda_bf16.h>
#include <math.h>

// Problem constants
#define BATCH 2
#define SEQ   2048
#define DMODEL 1024
#define NHEAD 16
#define DKH   64
#define MROWS (BATCH * SEQ)   // 4096

// ---------------- scratch (device globals, no allocation) ----------------
__device__ float g_qp[MROWS * DMODEL];
__device__ float g_kp[MROWS * DMODEL];
__device__ float g_vp[MROWS * DMODEL];
__device__ float g_ao[MROWS * DMODEL];

// ---------------- GEMM: C[M,N] = A[M,K] @ W[N,K]^T  (M=4096,N=K=1024) ----
#define BM 128
#define BN 128
#define BKK 8
#define TM 8
#define TN 8

__global__ __launch_bounds__(256, 2)
void sgemm_bt_kernel(const float* __restrict__ A,
                     const float* __restrict__ W,
                     float* __restrict__ C) {
    __shared__ float As[BKK][BM];
    __shared__ float Ws[BKK][BN];

    const int K = DMODEL;
    const int tid = threadIdx.x;
    const int tx = tid & 15;        // 0..15
    const int ty = tid >> 4;        // 0..15
    const int bm = blockIdx.y * BM;
    const int bn = blockIdx.x * BN;

    const int lrow = tid >> 1;        // 0..127
    const int lk   = (tid & 1) * 4;   // 0 or 4

    const float* Aptr = A + (size_t)(bm + lrow) * K + lk;
    const float* Wptr = W + (size_t)(bn + lrow) * K + lk;

    float acc[TM][TN];
    #pragma unroll
    for (int i = 0; i < TM; i++)
        #pragma unroll
        for (int j = 0; j < TN; j++) acc[i][j] = 0.0f;

    for (int k0 = 0; k0 < K; k0 += BKK) {
        float4 av = *reinterpret_cast<const float4*>(Aptr + k0);
        float4 wv = *reinterpret_cast<const float4*>(Wptr + k0);
        As[lk + 0][lrow] = av.x; As[lk + 1][lrow] = av.y;
        As[lk + 2][lrow] = av.z; As[lk + 3][lrow] = av.w;
        Ws[lk + 0][lrow] = wv.x; Ws[lk + 1][lrow] = wv.y;
        Ws[lk + 2][lrow] = wv.z; Ws[lk + 3][lrow] = wv.w;
        __syncthreads();

        #pragma unroll
        for (int k = 0; k < BKK; k++) {
            float a[TM], b[TN];
            float4 a0 = *reinterpret_cast<const float4*>(&As[k][ty * TM]);
            float4 a1 = *reinterpret_cast<const float4*>(&As[k][ty * TM + 4]);
            float4 b0 = *reinterpret_cast<const float4*>(&Ws[k][tx * TN]);
            float4 b1 = *reinterpret_cast<const float4*>(&Ws[k][tx * TN + 4]);
            a[0]=a0.x; a[1]=a0.y; a[2]=a0.z; a[3]=a0.w;
            a[4]=a1.x; a[5]=a1.y; a[6]=a1.z; a[7]=a1.w;
            b[0]=b0.x; b[1]=b0.y; b[2]=b0.z; b[3]=b0.w;
            b[4]=b1.x; b[5]=b1.y; b[6]=b1.z; b[7]=b1.w;
            #pragma unroll
            for (int i = 0; i < TM; i++)
                #pragma unroll
                for (int j = 0; j < TN; j++)
                    acc[i][j] += a[i] * b[j];
        }
        __syncthreads();
    }

    #pragma unroll
    for (int i = 0; i < TM; i++) {
        const int row = bm + ty * TM + i;
        float* Crow = C + (size_t)row * DMODEL + bn + tx * TN;
        float4 v0 = make_float4(acc[i][0], acc[i][1], acc[i][2], acc[i][3]);
        float4 v1 = make_float4(acc[i][4], acc[i][5], acc[i][6], acc[i][7]);
        *reinterpret_cast<float4*>(Crow)     = v0;
        *reinterpret_cast<float4*>(Crow + 4) = v1;
    }
}

// ---------------- Flash attention (fp32, causal) -------------------------
// Grid: (S/64, H, B). Block 256 threads. Each block: 64 query rows, one head.
// Online softmax over KV tiles of 64 rows.
#define QT 64
#define KT 64
#define SPAD 65   // padded width for Ss/KVs (conflict-free row scans)

__global__ __launch_bounds__(256, 2)
void flash_attn_kernel(const float* __restrict__ Q,
                       const float* __restrict__ Kp,
                       const float* __restrict__ Vp,
                       float* __restrict__ O) {
    extern __shared__ float sm[];
    float* Qs   = sm;                    // 64*64
    float* KVs  = Qs + QT * DKH;         // 64*65
    float* Ss   = KVs + KT * SPAD;       // 64*65
    float* m_s  = Ss + QT * SPAD;        // 64
    float* l_s  = m_s + QT;              // 64
    float* c_s  = l_s + QT;              // 64

    const int tid = threadIdx.x;
    const int tx = tid & 15;   // 0..15  -> 4 cols each
    const int ty = tid >> 4;   // 0..15  -> 4 rows each
    const int qi = blockIdx.x; // 0..31
    const int h  = blockIdx.y;
    const int b  = blockIdx.z;

    const size_t head_off = (size_t)b * SEQ * DMODEL + (size_t)h * DKH;
    const float* Qb = Q  + head_off;
    const float* Kb = Kp + head_off;
    const float* Vb = Vp + head_off;

    // Load Q tile [64 rows x 64 dims], row-major in smem (width 64)
    for (int idx = tid; idx < QT * (DKH / 4); idx += 256) {
        int r  = idx >> 4;           // row
        int c4 = (idx & 15) * 4;     // dim
        float4 v = *reinterpret_cast<const float4*>(
            Qb + (size_t)(qi * QT + r) * DMODEL + c4);
        Qs[r * DKH + c4 + 0] = v.x; Qs[r * DKH + c4 + 1] = v.y;
        Qs[r * DKH + c4 + 2] = v.z; Qs[r * DKH + c4 + 3] = v.w;
    }
    if (tid < QT) { m_s[tid] = -1e30f; l_s[tid] = 0.0f; }

    float o[4][4];
    #pragma unroll
    for (int i = 0; i < 4; i++)
        #pragma unroll
        for (int j = 0; j < 4; j++) o[i][j] = 0.0f;

    __syncthreads();

    for (int kt = 0; kt <= qi; kt++) {
        // ---- load K tile into KVs [j][d], width SPAD ----
        for (int idx = tid; idx < KT * (DKH / 4); idx += 256) {
            int r  = idx >> 4;
            int c4 = (idx & 15) * 4;
            float4 v = *reinterpret_cast<const float4*>(
                Kb + (size_t)(kt * KT + r) * DMODEL + c4);
            KVs[r * SPAD + c4 + 0] = v.x; KVs[r * SPAD + c4 + 1] = v.y;
            KVs[r * SPAD + c4 + 2] = v.z; KVs[r * SPAD + c4 + 3] = v.w;
        }
        __syncthreads();

        // ---- S = Q K^T * scale : each thread 4x4 ----
        float sacc[4][4];
        #pragma unroll
        for (int i = 0; i < 4; i++)
            #pragma unroll
            for (int j = 0; j < 4; j++) sacc[i][j] = 0.0f;

        #pragma unroll 8
        for (int d = 0; d < DKH; d++) {
            float a[4], bb[4];
            #pragma unroll
            for (int i = 0; i < 4; i++) a[i]  = Qs[(ty * 4 + i) * DKH + d];
            #pragma unroll
            for (int j = 0; j < 4; j++) bb[j] = KVs[(tx * 4 + j) * SPAD + d];
            #pragma unroll
            for (int i = 0; i < 4; i++)
                #pragma unroll
                for (int j = 0; j < 4; j++)
                    sacc[i][j] += a[i] * bb[j];
        }
        const float scale = 0.125f;  // 1/sqrt(64)
        #pragma unroll
        for (int i = 0; i < 4; i++)
            #pragma unroll
            for (int j = 0; j < 4; j++)
                Ss[(ty * 4 + i) * SPAD + tx * 4 + j] = sacc[i][j] * scale;
        __syncthreads();

        // ---- load V tile into KVs (K no longer needed) ----
        for (int idx = tid; idx < KT * (DKH / 4); idx += 256) {
            int r  = idx >> 4;
            int c4 = (idx & 15) * 4;
            float4 v = *reinterpret_cast<const float4*>(
                Vb + (size_t)(kt * KT + r) * DMODEL + c4);
            KVs[r * SPAD + c4 + 0] = v.x; KVs[r * SPAD + c4 + 1] = v.y;
            KVs[r * SPAD + c4 + 2] = v.z; KVs[r * SPAD + c4 + 3] = v.w;
        }

        // ---- online softmax per row (threads 0..63) ----
        if (tid < QT) {
            const int r = tid;
            const bool diag = (kt == qi);
            const int jmax = diag ? (r + 1) : KT;  // causal valid count
            float rowmax = -1e30f;
            for (int j = 0; j < jmax; j++)
                rowmax = fmaxf(rowmax, Ss[r * SPAD + j]);
            const float oldm = m_s[r];
            const float newm = fmaxf(oldm, rowmax);
            const float corr = __expf(oldm - newm);
            float lsum = 0.0f;
            for (int j = 0; j < KT; j++) {
                float p = (j < jmax) ? __expf(Ss[r * SPAD + j] - newm) : 0.0f;
                Ss[r * SPAD + j] = p;
                lsum += p;
            }
            l_s[r] = l_s[r] * corr + lsum;
            m_s[r] = newm;
            c_s[r] = corr;
        }
        __syncthreads();

        // ---- O = O*corr + P @ V : each thread 4 rows x 4 dims ----
        float cr[4];
        #pragma unroll
        for (int i = 0; i < 4; i++) cr[i] = c_s[ty * 4 + i];
        #pragma unroll
        for (int i = 0; i < 4; i++)
            #pragma unroll
            for (int j = 0; j < 4; j++) o[i][j] *= cr[i];

        #pragma unroll 8
        for (int j = 0; j < KT; j++) {
            float p[4], vv[4];
            #pragma unroll
            for (int i = 0; i < 4; i++) p[i]  = Ss[(ty * 4 + i) * SPAD + j];
            #pragma unroll
            for (int d = 0; d < 4; d++) vv[d] = KVs[j * SPAD + tx * 4 + d];
            #pragma unroll
            for (int i = 0; i < 4; i++)
                #pragma unroll
                for (int d = 0; d < 4; d++)
                    o[i][d] += p[i] * vv[d];
        }
        __syncthreads();
    }

    // ---- normalize and write out (layout [b, s, h*64+d]) ----
    #pragma unroll
    for (int i = 0; i < 4; i++) {
        const int r = ty * 4 + i;
        const float inv = 1.0f / l_s[r];
        const size_t out_off =
            ((size_t)b * SEQ + qi * QT + r) * DMODEL + h * DKH + tx * 4;
        float4 v = make_float4(o[i][0] * inv, o[i][1] * inv,
                               o[i][2] * inv, o[i][3] * inv);
        *reinterpret_cast<float4*>(O + out_off) = v;
    }
}

// ---------------- launch --------------------------------------------------
extern "C" void kernel_launch(void* const* d_in, const int* in_sizes, int n_in,
                              void* d_out, int out_size) {
    const float* q   = (const float*)d_in[0];
    const float* k   = (const float*)d_in[1];
    const float* v   = (const float*)d_in[2];
    // d_in[3] = mask (deterministic causal tril) — handled analytically
    const float* w_q = (const float*)d_in[4];
    const float* w_k = (const float*)d_in[5];
    const float* w_v = (const float*)d_in[6];
    const float* w_o = (const float*)d_in[7];
    float* out = (float*)d_out;

    float *qp, *kp, *vp, *ao;
    cudaGetSymbolAddress((void**)&qp, g_qp);
    cudaGetSymbolAddress((void**)&kp, g_kp);
    cudaGetSymbolAddress((void**)&vp, g_vp);
    cudaGetSymbolAddress((void**)&ao, g_ao);

    const int smem_bytes =
        (QT * DKH + 2 * KT * SPAD + 3 * QT) * (int)sizeof(float);  // 50432
    cudaFuncSetAttribute(flash_attn_kernel,
                         cudaFuncAttributeMaxDynamicSharedMemorySize,
                         smem_bytes);

    dim3 ggrid(DMODEL / BN, MROWS / BM);  // (8, 32)
    sgemm_bt_kernel<<<ggrid, 256>>>(q, w_q, qp);
    sgemm_bt_kernel<<<ggrid, 256>>>(k, w_k, kp);
    sgemm_bt_kernel<<<ggrid, 256>>>(v, w_v, vp);

    dim3 agrid(SEQ / QT, NHEAD, BATCH);   // (32, 16, 2)
    flash_attn_kernel<<<agrid, 256, smem_bytes>>>(qp, kp, vp, ao);

    sgemm_bt_kernel<<<ggrid, 256>>>(ao, w_o, out);
}

// round 3
// speedup vs baseline: 1.5206x; 1.5206x over previous
#include <cuda_runtime.h>
#include <cuda_bf16.h>
#include <math.h>
#include <stdint.h>

// Problem constants
#define BATCH 2
#define SEQ   2048
#define DMODEL 1024
#define NHEAD 16
#define DKH   64
#define MROWS (BATCH * SEQ)   // 4096

// ---------------- scratch (device globals, no allocation) ----------------
__device__ float g_qp[MROWS * DMODEL];
__device__ float g_kp[MROWS * DMODEL];
__device__ float g_vp[MROWS * DMODEL];
__device__ float g_ao[MROWS * DMODEL];
__device__ __nv_bfloat16 g_ah[MROWS * DMODEL];
__device__ __nv_bfloat16 g_al[MROWS * DMODEL];
__device__ __nv_bfloat16 g_wh[DMODEL * DMODEL];
__device__ __nv_bfloat16 g_wl[DMODEL * DMODEL];

// ================= small helpers ==========================================
__device__ __forceinline__ uint32_t smem_u32(const void* p) {
    return (uint32_t)__cvta_generic_to_shared(p);
}

__device__ __forceinline__ void ldsm_x4(uint32_t* r, uint32_t saddr) {
    asm volatile(
        "ldmatrix.sync.aligned.m8n8.x4.shared.b16 {%0,%1,%2,%3}, [%4];"
        : "=r"(r[0]), "=r"(r[1]), "=r"(r[2]), "=r"(r[3]) : "r"(saddr));
}

__device__ __forceinline__ void mma16816(float* d, const uint32_t* a,
                                         const uint32_t* b) {
    asm volatile(
        "mma.sync.aligned.m16n8k16.row.col.f32.bf16.bf16.f32 "
        "{%0,%1,%2,%3}, {%4,%5,%6,%7}, {%8,%9}, {%0,%1,%2,%3};"
        : "+f"(d[0]), "+f"(d[1]), "+f"(d[2]), "+f"(d[3])
        : "r"(a[0]), "r"(a[1]), "r"(a[2]), "r"(a[3]), "r"(b[0]), "r"(b[1]));
}

// ================= fp32 -> (bf16 hi, bf16 lo) split conversion ============
__global__ void cvt_split4_kernel(const float4* __restrict__ x,
                                  uint2* __restrict__ hi,
                                  uint2* __restrict__ lo, int n4) {
    int i = blockIdx.x * blockDim.x + threadIdx.x;
    if (i >= n4) return;
    float4 v = x[i];
    float a[4] = {v.x, v.y, v.z, v.w};
    union { __nv_bfloat16 b[4]; uint2 u; } H, L;
    #pragma unroll
    for (int j = 0; j < 4; j++) {
        __nv_bfloat16 h = __float2bfloat16(a[j]);
        float r = a[j] - __bfloat162float(h);
        H.b[j] = h;
        L.b[j] = __float2bfloat16(r);
    }
    hi[i] = H.u;
    lo[i] = L.u;
}

// ================= mma.sync GEMM: C[M,N] = A[M,K] @ W[N,K]^T ==============
// bf16x3: C = Ah*Wh + Ah*Wl + Al*Wh, fp32 accum.
// Block: 128x128 tile, 256 threads (8 warps, 4x2), BK=32, 2-stage cp.async.
#define BKG 32
#define NCH (DMODEL / BKG)   // 32 chunks
#define RSB 80               // smem row stride bytes (64B data + 16B pad)
#define TILEB (128 * RSB)    // 10240
#define STAGEB (4 * TILEB)   // 40960: Ah, Al, Wh, Wl
#define GSMEM (2 * STAGEB)   // 81920

__global__ __launch_bounds__(256)
void mma_gemm_bt(const __nv_bfloat16* __restrict__ Ah,
                 const __nv_bfloat16* __restrict__ Al,
                 const __nv_bfloat16* __restrict__ Wh,
                 const __nv_bfloat16* __restrict__ Wl,
                 float* __restrict__ C) {
    extern __shared__ char smc[];
    const uint32_t sb = smem_u32(smc);
    const int tid = threadIdx.x;
    const int lane = tid & 31;
    const int wid = tid >> 5;
    const int wm = wid >> 1;        // 0..3 -> 32-row slice
    const int wn = wid & 1;         // 0..1 -> 64-col slice
    const int m0 = blockIdx.y * 128;
    const int n0 = blockIdx.x * 128;

    // per-thread load pattern: 8 x 16B cp.async per stage
    const int lr = tid >> 2;            // row 0..63 (x2 halves)
    const int lg = tid & 3;             // 16B group

#define LOAD_STAGE(c, buf) do {                                              \
    const uint32_t sbase = sb + (buf) * STAGEB;                              \
    const int kc = (c) * BKG + lg * 8;                                       \
    const __nv_bfloat16* gp;                                                 \
    uint32_t sa;                                                             \
    _Pragma("unroll")                                                        \
    for (int half = 0; half < 2; half++) {                                   \
        const int r = half * 64 + lr;                                        \
        const size_t arow = (size_t)(m0 + r) * DMODEL + kc;                  \
        const size_t brow = (size_t)(n0 + r) * DMODEL + kc;                  \
        sa = sbase + 0 * TILEB + r * RSB + lg * 16; gp = Ah + arow;          \
        asm volatile("cp.async.cg.shared.global [%0], [%1], 16;"             \
                     :: "r"(sa), "l"(gp));                                   \
        sa = sbase + 1 * TILEB + r * RSB + lg * 16; gp = Al + arow;          \
        asm volatile("cp.async.cg.shared.global [%0], [%1], 16;"             \
                     :: "r"(sa), "l"(gp));                                   \
        sa = sbase + 2 * TILEB + r * RSB + lg * 16; gp = Wh + brow;          \
        asm volatile("cp.async.cg.shared.global [%0], [%1], 16;"             \
                     :: "r"(sa), "l"(gp));                                   \
        sa = sbase + 3 * TILEB + r * RSB + lg * 16; gp = Wl + brow;          \
        asm volatile("cp.async.cg.shared.global [%0], [%1], 16;"             \
                     :: "r"(sa), "l"(gp));                                   \
    }                                                                        \
    asm volatile("cp.async.commit_group;" ::: "memory");                     \
} while (0)

    float acc[2][8][4];
    #pragma unroll
    for (int mt = 0; mt < 2; mt++)
        #pragma unroll
        for (int nt = 0; nt < 8; nt++)
            #pragma unroll
            for (int q = 0; q < 4; q++) acc[mt][nt][q] = 0.0f;

    // ldmatrix lane addressing
    const int arow = (lane & 7) + ((lane >> 3) & 1) * 8;  // A: row in m16
    const int akh  = (lane >> 4) * 16;                    // A: k-half bytes
    const int brow = (lane & 7) + ((lane >> 4) & 1) * 8;  // B: n in n16 pair
    const int bkh  = ((lane >> 3) & 1) * 16;              // B: k-half bytes

    LOAD_STAGE(0, 0);

    for (int c = 0; c < NCH; c++) {
        const int buf = c & 1;
        if (c + 1 < NCH) {
            LOAD_STAGE(c + 1, (c + 1) & 1);
            asm volatile("cp.async.wait_group 1;" ::: "memory");
        } else {
            asm volatile("cp.async.wait_group 0;" ::: "memory");
        }
        __syncthreads();

        const uint32_t sAh = sb + buf * STAGEB + 0 * TILEB;
        const uint32_t sAl = sb + buf * STAGEB + 1 * TILEB;
        const uint32_t sWh = sb + buf * STAGEB + 2 * TILEB;
        const uint32_t sWl = sb + buf * STAGEB + 3 * TILEB;

        #pragma unroll
        for (int ks = 0; ks < 2; ks++) {
            uint32_t a_h[2][4], a_l[2][4];
            #pragma unroll
            for (int mt = 0; mt < 2; mt++) {
                const uint32_t ao =
                    (uint32_t)((wm * 32 + mt * 16 + arow) * RSB + ks * 32 + akh);
                ldsm_x4(a_h[mt], sAh + ao);
                ldsm_x4(a_l[mt], sAl + ao);
            }
            #pragma unroll
            for (int ntp = 0; ntp < 4; ntp++) {
                uint32_t bh[4], bl[4];
                const uint32_t bo =
                    (uint32_t)((wn * 64 + ntp * 16 + brow) * RSB + ks * 32 + bkh);
                ldsm_x4(bh, sWh + bo);
                ldsm_x4(bl, sWl + bo);
                #pragma unroll
                for (int hf = 0; hf < 2; hf++) {
                    const int nt = ntp * 2 + hf;
                    #pragma unroll
                    for (int mt = 0; mt < 2; mt++) {
                        mma16816(acc[mt][nt], a_h[mt], bh + 2 * hf);
                        mma16816(acc[mt][nt], a_l[mt], bh + 2 * hf);
                        mma16816(acc[mt][nt], a_h[mt], bl + 2 * hf);
                    }
                }
            }
        }
        __syncthreads();
    }

    // Epilogue: write fragments (f32) straight to global
    const int g = lane >> 2;
    const int cc = lane & 3;
    #pragma unroll
    for (int mt = 0; mt < 2; mt++) {
        #pragma unroll
        for (int nt = 0; nt < 8; nt++) {
            const int row = m0 + wm * 32 + mt * 16 + g;
            const int col = n0 + wn * 64 + nt * 8 + cc * 2;
            float2 v0 = make_float2(acc[mt][nt][0], acc[mt][nt][1]);
            float2 v1 = make_float2(acc[mt][nt][2], acc[mt][nt][3]);
            *reinterpret_cast<float2*>(&C[(size_t)row * DMODEL + col]) = v0;
            *reinterpret_cast<float2*>(&C[(size_t)(row + 8) * DMODEL + col]) = v1;
        }
    }
#undef LOAD_STAGE
}

// ---------------- Flash attention (fp32, causal) — UNCHANGED from R1 ----
#define QT 64
#define KT 64
#define SPAD 65

__global__ __launch_bounds__(256, 2)
void flash_attn_kernel(const float* __restrict__ Q,
                       const float* __restrict__ Kp,
                       const float* __restrict__ Vp,
                       float* __restrict__ O) {
    extern __shared__ float sm[];
    float* Qs   = sm;
    float* KVs  = Qs + QT * DKH;
    float* Ss   = KVs + KT * SPAD;
    float* m_s  = Ss + QT * SPAD;
    float* l_s  = m_s + QT;
    float* c_s  = l_s + QT;

    const int tid = threadIdx.x;
    const int tx = tid & 15;
    const int ty = tid >> 4;
    const int qi = blockIdx.x;
    const int h  = blockIdx.y;
    const int b  = blockIdx.z;

    const size_t head_off = (size_t)b * SEQ * DMODEL + (size_t)h * DKH;
    const float* Qb = Q  + head_off;
    const float* Kb = Kp + head_off;
    const float* Vb = Vp + head_off;

    for (int idx = tid; idx < QT * (DKH / 4); idx += 256) {
        int r  = idx >> 4;
        int c4 = (idx & 15) * 4;
        float4 v = *reinterpret_cast<const float4*>(
            Qb + (size_t)(qi * QT + r) * DMODEL + c4);
        Qs[r * DKH + c4 + 0] = v.x; Qs[r * DKH + c4 + 1] = v.y;
        Qs[r * DKH + c4 + 2] = v.z; Qs[r * DKH + c4 + 3] = v.w;
    }
    if (tid < QT) { m_s[tid] = -1e30f; l_s[tid] = 0.0f; }

    float o[4][4];
    #pragma unroll
    for (int i = 0; i < 4; i++)
        #pragma unroll
        for (int j = 0; j < 4; j++) o[i][j] = 0.0f;

    __syncthreads();

    for (int kt = 0; kt <= qi; kt++) {
        for (int idx = tid; idx < KT * (DKH / 4); idx += 256) {
            int r  = idx >> 4;
            int c4 = (idx & 15) * 4;
            float4 v = *reinterpret_cast<const float4*>(
                Kb + (size_t)(kt * KT + r) * DMODEL + c4);
            KVs[r * SPAD + c4 + 0] = v.x; KVs[r * SPAD + c4 + 1] = v.y;
            KVs[r * SPAD + c4 + 2] = v.z; KVs[r * SPAD + c4 + 3] = v.w;
        }
        __syncthreads();

        float sacc[4][4];
        #pragma unroll
        for (int i = 0; i < 4; i++)
            #pragma unroll
            for (int j = 0; j < 4; j++) sacc[i][j] = 0.0f;

        #pragma unroll 8
        for (int d = 0; d < DKH; d++) {
            float a[4], bb[4];
            #pragma unroll
            for (int i = 0; i < 4; i++) a[i]  = Qs[(ty * 4 + i) * DKH + d];
            #pragma unroll
            for (int j = 0; j < 4; j++) bb[j] = KVs[(tx * 4 + j) * SPAD + d];
            #pragma unroll
            for (int i = 0; i < 4; i++)
                #pragma unroll
                for (int j = 0; j < 4; j++)
                    sacc[i][j] += a[i] * bb[j];
        }
        const float scale = 0.125f;
        #pragma unroll
        for (int i = 0; i < 4; i++)
            #pragma unroll
            for (int j = 0; j < 4; j++)
                Ss[(ty * 4 + i) * SPAD + tx * 4 + j] = sacc[i][j] * scale;
        __syncthreads();

        for (int idx = tid; idx < KT * (DKH / 4); idx += 256) {
            int r  = idx >> 4;
            int c4 = (idx & 15) * 4;
            float4 v = *reinterpret_cast<const float4*>(
                Vb + (size_t)(kt * KT + r) * DMODEL + c4);
            KVs[r * SPAD + c4 + 0] = v.x; KVs[r * SPAD + c4 + 1] = v.y;
            KVs[r * SPAD + c4 + 2] = v.z; KVs[r * SPAD + c4 + 3] = v.w;
        }

        if (tid < QT) {
            const int r = tid;
            const bool diag = (kt == qi);
            const int jmax = diag ? (r + 1) : KT;
            float rowmax = -1e30f;
            for (int j = 0; j < jmax; j++)
                rowmax = fmaxf(rowmax, Ss[r * SPAD + j]);
            const float oldm = m_s[r];
            const float newm = fmaxf(oldm, rowmax);
            const float corr = __expf(oldm - newm);
            float lsum = 0.0f;
            for (int j = 0; j < KT; j++) {
                float p = (j < jmax) ? __expf(Ss[r * SPAD + j] - newm) : 0.0f;
                Ss[r * SPAD + j] = p;
                lsum += p;
            }
            l_s[r] = l_s[r] * corr + lsum;
            m_s[r] = newm;
            c_s[r] = corr;
        }
        __syncthreads();

        float cr[4];
        #pragma unroll
        for (int i = 0; i < 4; i++) cr[i] = c_s[ty * 4 + i];
        #pragma unroll
        for (int i = 0; i < 4; i++)
            #pragma unroll
            for (int j = 0; j < 4; j++) o[i][j] *= cr[i];

        #pragma unroll 8
        for (int j = 0; j < KT; j++) {
            float p[4], vv[4];
            #pragma unroll
            for (int i = 0; i < 4; i++) p[i]  = Ss[(ty * 4 + i) * SPAD + j];
            #pragma unroll
            for (int d = 0; d < 4; d++) vv[d] = KVs[j * SPAD + tx * 4 + d];
            #pragma unroll
            for (int i = 0; i < 4; i++)
                #pragma unroll
                for (int d = 0; d < 4; d++)
                    o[i][d] += p[i] * vv[d];
        }
        __syncthreads();
    }

    #pragma unroll
    for (int i = 0; i < 4; i++) {
        const int r = ty * 4 + i;
        const float inv = 1.0f / l_s[r];
        const size_t out_off =
            ((size_t)b * SEQ + qi * QT + r) * DMODEL + h * DKH + tx * 4;
        float4 v = make_float4(o[i][0] * inv, o[i][1] * inv,
                               o[i][2] * inv, o[i][3] * inv);
        *reinterpret_cast<float4*>(O + out_off) = v;
    }
}

// ---------------- launch --------------------------------------------------
extern "C" void kernel_launch(void* const* d_in, const int* in_sizes, int n_in,
                              void* d_out, int out_size) {
    const float* q   = (const float*)d_in[0];
    const float* k   = (const float*)d_in[1];
    const float* v   = (const float*)d_in[2];
    // d_in[3] = mask (deterministic causal tril) — handled analytically
    const float* w_q = (const float*)d_in[4];
    const float* w_k = (const float*)d_in[5];
    const float* w_v = (const float*)d_in[6];
    const float* w_o = (const float*)d_in[7];
    float* out = (float*)d_out;

    float *qp, *kp, *vp, *ao;
    __nv_bfloat16 *ah, *al, *wh, *wl;
    cudaGetSymbolAddress((void**)&qp, g_qp);
    cudaGetSymbolAddress((void**)&kp, g_kp);
    cudaGetSymbolAddress((void**)&vp, g_vp);
    cudaGetSymbolAddress((void**)&ao, g_ao);
    cudaGetSymbolAddress((void**)&ah, g_ah);
    cudaGetSymbolAddress((void**)&al, g_al);
    cudaGetSymbolAddress((void**)&wh, g_wh);
    cudaGetSymbolAddress((void**)&wl, g_wl);

    cudaFuncSetAttribute(mma_gemm_bt,
                         cudaFuncAttributeMaxDynamicSharedMemorySize, GSMEM);
    const int flash_smem =
        (QT * DKH + 2 * KT * SPAD + 3 * QT) * (int)sizeof(float);
    cudaFuncSetAttribute(flash_attn_kernel,
                         cudaFuncAttributeMaxDynamicSharedMemorySize,
                         flash_smem);

    const int nA4 = MROWS * DMODEL / 4;   // 1048576
    const int nW4 = DMODEL * DMODEL / 4;  // 262144
    dim3 ggrid(DMODEL / 128, MROWS / 128);  // (8, 32)

    // Q projection
    cvt_split4_kernel<<<nA4 / 256, 256>>>((const float4*)q, (uint2*)ah, (uint2*)al, nA4);
    cvt_split4_kernel<<<nW4 / 256, 256>>>((const float4*)w_q, (uint2*)wh, (uint2*)wl, nW4);
    mma_gemm_bt<<<ggrid, 256, GSMEM>>>(ah, al, wh, wl, qp);
    // K projection
    cvt_split4_kernel<<<nA4 / 256, 256>>>((const float4*)k, (uint2*)ah, (uint2*)al, nA4);
    cvt_split4_kernel<<<nW4 / 256, 256>>>((const float4*)w_k, (uint2*)wh, (uint2*)wl, nW4);
    mma_gemm_bt<<<ggrid, 256, GSMEM>>>(ah, al, wh, wl, kp);
    // V projection
    cvt_split4_kernel<<<nA4 / 256, 256>>>((const float4*)v, (uint2*)ah, (uint2*)al, nA4);
    cvt_split4_kernel<<<nW4 / 256, 256>>>((const float4*)w_v, (uint2*)wh, (uint2*)wl, nW4);
    mma_gemm_bt<<<ggrid, 256, GSMEM>>>(ah, al, wh, wl, vp);

    // Attention
    dim3 agrid(SEQ / QT, NHEAD, BATCH);
    flash_attn_kernel<<<agrid, 256, flash_smem>>>(qp, kp, vp, ao);

    // Output projection
    cvt_split4_kernel<<<nA4 / 256, 256>>>((const float4*)ao, (uint2*)ah, (uint2*)al, nA4);
    cvt_split4_kernel<<<nW4 / 256, 256>>>((const float4*)w_o, (uint2*)wh, (uint2*)wl, nW4);
    mma_gemm_bt<<<ggrid, 256, GSMEM>>>(ah, al, wh, wl, out);
}

// round 4
// speedup vs baseline: 3.0281x; 1.9914x over previous
#include <cuda_runtime.h>
#include <cuda_bf16.h>
#include <math.h>
#include <stdint.h>

// Problem constants
#define BATCH 2
#define SEQ   2048
#define DMODEL 1024
#define NHEAD 16
#define DKH   64
#define MROWS (BATCH * SEQ)   // 4096

// scale folded into Q projection: 1/sqrt(64) * log2(e)
#define QSCALE 0.18033688011112042f

// ---------------- scratch (device globals, no allocation) ----------------
__device__ __nv_bfloat16 g_ah[MROWS * DMODEL];
__device__ __nv_bfloat16 g_al[MROWS * DMODEL];
__device__ __nv_bfloat16 g_wh[DMODEL * DMODEL];
__device__ __nv_bfloat16 g_wl[DMODEL * DMODEL];
__device__ __nv_bfloat16 g_qh[MROWS * DMODEL];
__device__ __nv_bfloat16 g_ql[MROWS * DMODEL];
__device__ __nv_bfloat16 g_kh[MROWS * DMODEL];
__device__ __nv_bfloat16 g_kl[MROWS * DMODEL];
__device__ __nv_bfloat16 g_vh[MROWS * DMODEL];
__device__ __nv_bfloat16 g_vl[MROWS * DMODEL];

// ================= small helpers ==========================================
__device__ __forceinline__ uint32_t smem_u32(const void* p) {
    return (uint32_t)__cvta_generic_to_shared(p);
}

__device__ __forceinline__ void ldsm_x4(uint32_t* r, uint32_t saddr) {
    asm volatile(
        "ldmatrix.sync.aligned.m8n8.x4.shared.b16 {%0,%1,%2,%3}, [%4];"
        : "=r"(r[0]), "=r"(r[1]), "=r"(r[2]), "=r"(r[3]) : "r"(saddr));
}

__device__ __forceinline__ void ldsm_x4_t(uint32_t* r, uint32_t saddr) {
    asm volatile(
        "ldmatrix.sync.aligned.m8n8.x4.trans.shared.b16 {%0,%1,%2,%3}, [%4];"
        : "=r"(r[0]), "=r"(r[1]), "=r"(r[2]), "=r"(r[3]) : "r"(saddr));
}

__device__ __forceinline__ void mma16816(float* d, const uint32_t* a,
                                         const uint32_t* b) {
    asm volatile(
        "mma.sync.aligned.m16n8k16.row.col.f32.bf16.bf16.f32 "
        "{%0,%1,%2,%3}, {%4,%5,%6,%7}, {%8,%9}, {%0,%1,%2,%3};"
        : "+f"(d[0]), "+f"(d[1]), "+f"(d[2]), "+f"(d[3])
        : "r"(a[0]), "r"(a[1]), "r"(a[2]), "r"(a[3]), "r"(b[0]), "r"(b[1]));
}

__device__ __forceinline__ void cpasync16(uint32_t s, const void* g) {
    asm volatile("cp.async.cg.shared.global [%0], [%1], 16;"
                 :: "r"(s), "l"(g));
}

// pack two fp32 -> bf16x2 (hi in upper half) + residual bf16x2
__device__ __forceinline__ void split_pack(float x0, float x1,
                                           uint32_t& hp, uint32_t& lp) {
    asm("cvt.rn.bf16x2.f32 %0, %1, %2;" : "=r"(hp) : "f"(x1), "f"(x0));
    float f0 = __uint_as_float(hp << 16);
    float f1 = __uint_as_float(hp & 0xffff0000u);
    asm("cvt.rn.bf16x2.f32 %0, %1, %2;" : "=r"(lp)
        : "f"(x1 - f1), "f"(x0 - f0));
}

// ================= fp32 -> (bf16 hi, bf16 lo) split conversion ============
__global__ void cvt_split4_kernel(const float4* __restrict__ x,
                                  uint2* __restrict__ hi,
                                  uint2* __restrict__ lo, int n4) {
    int i = blockIdx.x * blockDim.x + threadIdx.x;
    if (i >= n4) return;
    float4 v = x[i];
    float a[4] = {v.x, v.y, v.z, v.w};
    union { __nv_bfloat16 b[4]; uint2 u; } H, L;
    #pragma unroll
    for (int j = 0; j < 4; j++) {
        __nv_bfloat16 h = __float2bfloat16(a[j]);
        float r = a[j] - __bfloat162float(h);
        H.b[j] = h;
        L.b[j] = __float2bfloat16(r);
    }
    hi[i] = H.u;
    lo[i] = L.u;
}

// ================= mma.sync GEMM: C[M,N] = A[M,K] @ W[N,K]^T ==============
// bf16x3: C = Ah*Wh + Ah*Wl + Al*Wh, fp32 accum.
// Epilogue: fp32 (Cf) or scaled bf16 hi/lo split (Ch/Cl).
#define BKG 32
#define NCH (DMODEL / BKG)   // 32 chunks
#define RSB 80               // smem row stride bytes (64B data + 16B pad)
#define TILEB (128 * RSB)    // 10240
#define STAGEB (4 * TILEB)   // 40960
#define GSMEM (2 * STAGEB)   // 81920

__global__ __launch_bounds__(256)
void mma_gemm_bt(const __nv_bfloat16* __restrict__ Ah,
                 const __nv_bfloat16* __restrict__ Al,
                 const __nv_bfloat16* __restrict__ Wh,
                 const __nv_bfloat16* __restrict__ Wl,
                 float* __restrict__ Cf,
                 __nv_bfloat16* __restrict__ Ch,
                 __nv_bfloat16* __restrict__ Cl,
                 float osc) {
    extern __shared__ char smc[];
    const uint32_t sb = smem_u32(smc);
    const int tid = threadIdx.x;
    const int lane = tid & 31;
    const int wid = tid >> 5;
    const int wm = wid >> 1;
    const int wn = wid & 1;
    const int m0 = blockIdx.y * 128;
    const int n0 = blockIdx.x * 128;

    const int lr = tid >> 2;
    const int lg = tid & 3;

#define LOAD_STAGE(c, buf) do {                                              \
    const uint32_t sbase = sb + (buf) * STAGEB;                              \
    const int kc = (c) * BKG + lg * 8;                                       \
    _Pragma("unroll")                                                        \
    for (int half = 0; half < 2; half++) {                                   \
        const int r = half * 64 + lr;                                        \
        const size_t arow = (size_t)(m0 + r) * DMODEL + kc;                  \
        const size_t brow = (size_t)(n0 + r) * DMODEL + kc;                  \
        cpasync16(sbase + 0 * TILEB + r * RSB + lg * 16, Ah + arow);         \
        cpasync16(sbase + 1 * TILEB + r * RSB + lg * 16, Al + arow);         \
        cpasync16(sbase + 2 * TILEB + r * RSB + lg * 16, Wh + brow);         \
        cpasync16(sbase + 3 * TILEB + r * RSB + lg * 16, Wl + brow);         \
    }                                                                        \
    asm volatile("cp.async.commit_group;" ::: "memory");                     \
} while (0)

    float acc[2][8][4];
    #pragma unroll
    for (int mt = 0; mt < 2; mt++)
        #pragma unroll
        for (int nt = 0; nt < 8; nt++)
            #pragma unroll
            for (int q = 0; q < 4; q++) acc[mt][nt][q] = 0.0f;

    const int arow = (lane & 7) + ((lane >> 3) & 1) * 8;
    const int akh  = (lane >> 4) * 16;
    const int brow = (lane & 7) + ((lane >> 4) & 1) * 8;
    const int bkh  = ((lane >> 3) & 1) * 16;

    LOAD_STAGE(0, 0);

    for (int c = 0; c < NCH; c++) {
        const int buf = c & 1;
        if (c + 1 < NCH) {
            LOAD_STAGE(c + 1, (c + 1) & 1);
            asm volatile("cp.async.wait_group 1;" ::: "memory");
        } else {
            asm volatile("cp.async.wait_group 0;" ::: "memory");
        }
        __syncthreads();

        const uint32_t sAh = sb + buf * STAGEB + 0 * TILEB;
        const uint32_t sAl = sb + buf * STAGEB + 1 * TILEB;
        const uint32_t sWh = sb + buf * STAGEB + 2 * TILEB;
        const uint32_t sWl = sb + buf * STAGEB + 3 * TILEB;

        #pragma unroll
        for (int ks = 0; ks < 2; ks++) {
            uint32_t a_h[2][4], a_l[2][4];
            #pragma unroll
            for (int mt = 0; mt < 2; mt++) {
                const uint32_t ao =
                    (uint32_t)((wm * 32 + mt * 16 + arow) * RSB + ks * 32 + akh);
                ldsm_x4(a_h[mt], sAh + ao);
                ldsm_x4(a_l[mt], sAl + ao);
            }
            #pragma unroll
            for (int ntp = 0; ntp < 4; ntp++) {
                uint32_t bh[4], bl[4];
                const uint32_t bo =
                    (uint32_t)((wn * 64 + ntp * 16 + brow) * RSB + ks * 32 + bkh);
                ldsm_x4(bh, sWh + bo);
                ldsm_x4(bl, sWl + bo);
                #pragma unroll
                for (int hf = 0; hf < 2; hf++) {
                    const int nt = ntp * 2 + hf;
                    #pragma unroll
                    for (int mt = 0; mt < 2; mt++) {
                        mma16816(acc[mt][nt], a_h[mt], bh + 2 * hf);
                        mma16816(acc[mt][nt], a_l[mt], bh + 2 * hf);
                        mma16816(acc[mt][nt], a_h[mt], bl + 2 * hf);
                    }
                }
            }
        }
        __syncthreads();
    }

    const int g = lane >> 2;
    const int cc = lane & 3;
    if (Cf != nullptr) {
        #pragma unroll
        for (int mt = 0; mt < 2; mt++) {
            #pragma unroll
            for (int nt = 0; nt < 8; nt++) {
                const int row = m0 + wm * 32 + mt * 16 + g;
                const int col = n0 + wn * 64 + nt * 8 + cc * 2;
                float2 v0 = make_float2(acc[mt][nt][0], acc[mt][nt][1]);
                float2 v1 = make_float2(acc[mt][nt][2], acc[mt][nt][3]);
                *reinterpret_cast<float2*>(&Cf[(size_t)row * DMODEL + col]) = v0;
                *reinterpret_cast<float2*>(&Cf[(size_t)(row + 8) * DMODEL + col]) = v1;
            }
        }
    } else {
        #pragma unroll
        for (int mt = 0; mt < 2; mt++) {
            #pragma unroll
            for (int nt = 0; nt < 8; nt++) {
                const int row = m0 + wm * 32 + mt * 16 + g;
                const int col = n0 + wn * 64 + nt * 8 + cc * 2;
                uint32_t h01, l01, h23, l23;
                split_pack(acc[mt][nt][0] * osc, acc[mt][nt][1] * osc, h01, l01);
                split_pack(acc[mt][nt][2] * osc, acc[mt][nt][3] * osc, h23, l23);
                *reinterpret_cast<uint32_t*>(&Ch[(size_t)row * DMODEL + col]) = h01;
                *reinterpret_cast<uint32_t*>(&Cl[(size_t)row * DMODEL + col]) = l01;
                *reinterpret_cast<uint32_t*>(&Ch[(size_t)(row + 8) * DMODEL + col]) = h23;
                *reinterpret_cast<uint32_t*>(&Cl[(size_t)(row + 8) * DMODEL + col]) = l23;
            }
        }
    }
#undef LOAD_STAGE
}

// ================= mma.sync flash attention (causal, bf16x3) ==============
// CTA: 128 q-rows x one (b,h). 8 warps x m16. K/V tiles 64, double-buffered.
#define RSF 144                 // 128B data + 16B pad
#define FS_QH 0
#define FS_QL (128 * RSF)       // 18432
#define FS_KV0 (2 * 128 * RSF)  // 36864
#define KVT (64 * RSF)          // 9216
#define FSTAGE (4 * KVT)        // 36864
#define FLASH_SMEM (FS_KV0 + 2 * FSTAGE)  // 110592

__global__ __launch_bounds__(256, 1)
void flash_mma_kernel(const __nv_bfloat16* __restrict__ Qh,
                      const __nv_bfloat16* __restrict__ Ql,
                      const __nv_bfloat16* __restrict__ Kh,
                      const __nv_bfloat16* __restrict__ Kl,
                      const __nv_bfloat16* __restrict__ Vh,
                      const __nv_bfloat16* __restrict__ Vl,
                      __nv_bfloat16* __restrict__ Oh,
                      __nv_bfloat16* __restrict__ Ol) {
    extern __shared__ char sm8[];
    const uint32_t sb = smem_u32(sm8);
    const int tid = threadIdx.x;
    const int lane = tid & 31;
    const int wm = tid >> 5;                     // warp 0..7 -> 16 rows each
    const int qi = (int)gridDim.x - 1 - (int)blockIdx.x;  // heavy blocks first
    const int h = blockIdx.y;
    const int b = blockIdx.z;
    const int nkt = 2 * qi + 2;
    const size_t hoff = (size_t)h * DKH;

#define LOAD_KV(kt, bufi) do {                                               \
    const int r_ = tid >> 2;                                                 \
    const int g0_ = tid & 3;                                                 \
    const size_t grow_ =                                                     \
        (size_t)(b * SEQ + (kt) * 64 + r_) * DMODEL + hoff;                  \
    const uint32_t sbase_ = sb + FS_KV0 + (bufi) * FSTAGE;                   \
    _Pragma("unroll")                                                        \
    for (int gg = 0; gg < 2; gg++) {                                         \
        const int g_ = g0_ + gg * 4;                                         \
        const uint32_t so_ = r_ * RSF + g_ * 16;                             \
        cpasync16(sbase_ + 0 * KVT + so_, Kh + grow_ + g_ * 8);              \
        cpasync16(sbase_ + 1 * KVT + so_, Kl + grow_ + g_ * 8);              \
        cpasync16(sbase_ + 2 * KVT + so_, Vh + grow_ + g_ * 8);              \
        cpasync16(sbase_ + 3 * KVT + so_, Vl + grow_ + g_ * 8);              \
    }                                                                        \
    asm volatile("cp.async.commit_group;" ::: "memory");                     \
} while (0)

    // Q tile cp.async (group 0, together with KV stage 0)
    {
        const int r = tid >> 1;
        const int g0 = (tid & 1) * 4;
        const size_t grow = (size_t)(b * SEQ + qi * 128 + r) * DMODEL + hoff;
        #pragma unroll
        for (int gg = 0; gg < 4; gg++) {
            const int g = g0 + gg;
            const uint32_t so = r * RSF + g * 16;
            cpasync16(sb + FS_QH + so, Qh + grow + g * 8);
            cpasync16(sb + FS_QL + so, Ql + grow + g * 8);
        }
    }
    LOAD_KV(0, 0);

    float m0 = -1e30f, m1 = -1e30f, l0 = 0.0f, l1 = 0.0f;
    float o[8][4];
    #pragma unroll
    for (int f = 0; f < 8; f++)
        #pragma unroll
        for (int q = 0; q < 4; q++) o[f][q] = 0.0f;

    uint32_t qhf[4][4], qlf[4][4];

    const int ar = lane & 15;             // A/V-trans row select
    const int ac = (lane >> 4) * 16;      // A/V-trans 16B column select
    const int br = (lane & 7) + ((lane >> 4) & 1) * 8;  // K (B) row select
    const int bk = ((lane >> 3) & 1) * 16;              // K (B) k-half

    for (int kt = 0; kt < nkt; kt++) {
        const int buf = kt & 1;
        if (kt + 1 < nkt) {
            LOAD_KV(kt + 1, (kt + 1) & 1);
            asm volatile("cp.async.wait_group 1;" ::: "memory");
        } else {
            asm volatile("cp.async.wait_group 0;" ::: "memory");
        }
        __syncthreads();

        if (kt == 0) {
            #pragma unroll
            for (int ks = 0; ks < 4; ks++) {
                const uint32_t qa =
                    sb + FS_QH + (wm * 16 + ar) * RSF + ks * 32 + ac;
                ldsm_x4(qhf[ks], qa);
                ldsm_x4(qlf[ks], qa + (FS_QL - FS_QH));
            }
        }

        const uint32_t sK = sb + FS_KV0 + buf * FSTAGE;
        const uint32_t sV = sK + 2 * KVT;

        // ---- S = Qs @ K^T (bf16x3) ----
        float s[8][4];
        #pragma unroll
        for (int f = 0; f < 8; f++)
            #pragma unroll
            for (int q = 0; q < 4; q++) s[f][q] = 0.0f;

        #pragma unroll
        for (int ks = 0; ks < 4; ks++) {
            #pragma unroll
            for (int np = 0; np < 4; np++) {
                uint32_t kbh[4], kbl[4];
                const uint32_t ka = sK + (np * 16 + br) * RSF + ks * 32 + bk;
                ldsm_x4(kbh, ka);
                ldsm_x4(kbl, ka + KVT);
                #pragma unroll
                for (int hf = 0; hf < 2; hf++) {
                    const int nt = np * 2 + hf;
                    mma16816(s[nt], qhf[ks], kbh + 2 * hf);
                    mma16816(s[nt], qhf[ks], kbl + 2 * hf);
                    mma16816(s[nt], qlf[ks], kbh + 2 * hf);
                }
            }
        }

        // ---- causal mask (diagonal tiles only) ----
        if (kt >= 2 * qi) {
            const int grow = qi * 128 + wm * 16 + (lane >> 2);
            const int gc = kt * 64 + (lane & 3) * 2;
            #pragma unroll
            for (int f = 0; f < 8; f++) {
                const int c = gc + f * 8;
                if (c > grow)         s[f][0] = -1e30f;
                if (c + 1 > grow)     s[f][1] = -1e30f;
                if (c > grow + 8)     s[f][2] = -1e30f;
                if (c + 1 > grow + 8) s[f][3] = -1e30f;
            }
        }

        // ---- online softmax (exp2 domain; scale folded into Q) ----
        float mx0 = -1e30f, mx1 = -1e30f;
        #pragma unroll
        for (int f = 0; f < 8; f++) {
            mx0 = fmaxf(mx0, fmaxf(s[f][0], s[f][1]));
            mx1 = fmaxf(mx1, fmaxf(s[f][2], s[f][3]));
        }
        mx0 = fmaxf(mx0, __shfl_xor_sync(0xffffffffu, mx0, 1));
        mx0 = fmaxf(mx0, __shfl_xor_sync(0xffffffffu, mx0, 2));
        mx1 = fmaxf(mx1, __shfl_xor_sync(0xffffffffu, mx1, 1));
        mx1 = fmaxf(mx1, __shfl_xor_sync(0xffffffffu, mx1, 2));

        const float nm0 = fmaxf(m0, mx0);
        const float nm1 = fmaxf(m1, mx1);
        const float c0 = exp2f(m0 - nm0);
        const float c1 = exp2f(m1 - nm1);
        float r0 = 0.0f, r1 = 0.0f;
        #pragma unroll
        for (int f = 0; f < 8; f++) {
            s[f][0] = exp2f(s[f][0] - nm0);
            s[f][1] = exp2f(s[f][1] - nm0);
            s[f][2] = exp2f(s[f][2] - nm1);
            s[f][3] = exp2f(s[f][3] - nm1);
            r0 += s[f][0] + s[f][1];
            r1 += s[f][2] + s[f][3];
        }
        r0 += __shfl_xor_sync(0xffffffffu, r0, 1);
        r0 += __shfl_xor_sync(0xffffffffu, r0, 2);
        r1 += __shfl_xor_sync(0xffffffffu, r1, 1);
        r1 += __shfl_xor_sync(0xffffffffu, r1, 2);
        l0 = l0 * c0 + r0;  m0 = nm0;
        l1 = l1 * c1 + r1;  m1 = nm1;
        #pragma unroll
        for (int f = 0; f < 8; f++) {
            o[f][0] *= c0; o[f][1] *= c0;
            o[f][2] *= c1; o[f][3] *= c1;
        }

        // ---- pack P into A-fragments (hi + residual) ----
        uint32_t ph[4][4], pl[4][4];
        #pragma unroll
        for (int j = 0; j < 4; j++) {
            split_pack(s[2 * j][0],     s[2 * j][1],     ph[j][0], pl[j][0]);
            split_pack(s[2 * j][2],     s[2 * j][3],     ph[j][1], pl[j][1]);
            split_pack(s[2 * j + 1][0], s[2 * j + 1][1], ph[j][2], pl[j][2]);
            split_pack(s[2 * j + 1][2], s[2 * j + 1][3], ph[j][3], pl[j][3]);
        }

        // ---- O += P @ V (bf16x3, V via trans ldmatrix) ----
        #pragma unroll
        for (int ks = 0; ks < 4; ks++) {
            #pragma unroll
            for (int np = 0; np < 4; np++) {
                uint32_t vbh[4], vbl[4];
                const uint32_t va = sV + (ks * 16 + ar) * RSF + np * 32 + ac;
                ldsm_x4_t(vbh, va);
                ldsm_x4_t(vbl, va + KVT);
                #pragma unroll
                for (int hf = 0; hf < 2; hf++) {
                    const int nt = np * 2 + hf;
                    mma16816(o[nt], ph[ks], vbh + 2 * hf);
                    mma16816(o[nt], ph[ks], vbl + 2 * hf);
                    mma16816(o[nt], pl[ks], vbh + 2 * hf);
                }
            }
        }
        __syncthreads();
    }

    // ---- epilogue: normalize, split to bf16 hi/lo, store ----
    const float i0 = 1.0f / l0;
    const float i1 = 1.0f / l1;
    const size_t row0 = (size_t)(b * SEQ + qi * 128 + wm * 16 + (lane >> 2));
    const int colb = (int)hoff + (lane & 3) * 2;
    #pragma unroll
    for (int f = 0; f < 8; f++) {
        const size_t off0 = row0 * DMODEL + colb + f * 8;
        const size_t off1 = (row0 + 8) * DMODEL + colb + f * 8;
        uint32_t h01, l01, h23, l23;
        split_pack(o[f][0] * i0, o[f][1] * i0, h01, l01);
        split_pack(o[f][2] * i1, o[f][3] * i1, h23, l23);
        *reinterpret_cast<uint32_t*>(&Oh[off0]) = h01;
        *reinterpret_cast<uint32_t*>(&Ol[off0]) = l01;
        *reinterpret_cast<uint32_t*>(&Oh[off1]) = h23;
        *reinterpret_cast<uint32_t*>(&Ol[off1]) = l23;
    }
#undef LOAD_KV
}

// ---------------- launch --------------------------------------------------
extern "C" void kernel_launch(void* const* d_in, const int* in_sizes, int n_in,
                              void* d_out, int out_size) {
    const float* q   = (const float*)d_in[0];
    const float* k   = (const float*)d_in[1];
    const float* v   = (const float*)d_in[2];
    // d_in[3] = mask (deterministic causal tril) — handled analytically
    const float* w_q = (const float*)d_in[4];
    const float* w_k = (const float*)d_in[5];
    const float* w_v = (const float*)d_in[6];
    const float* w_o = (const float*)d_in[7];
    float* out = (float*)d_out;

    __nv_bfloat16 *ah, *al, *wh, *wl, *qh, *ql, *kh, *kl, *vh, *vl;
    cudaGetSymbolAddress((void**)&ah, g_ah);
    cudaGetSymbolAddress((void**)&al, g_al);
    cudaGetSymbolAddress((void**)&wh, g_wh);
    cudaGetSymbolAddress((void**)&wl, g_wl);
    cudaGetSymbolAddress((void**)&qh, g_qh);
    cudaGetSymbolAddress((void**)&ql, g_ql);
    cudaGetSymbolAddress((void**)&kh, g_kh);
    cudaGetSymbolAddress((void**)&kl, g_kl);
    cudaGetSymbolAddress((void**)&vh, g_vh);
    cudaGetSymbolAddress((void**)&vl, g_vl);

    cudaFuncSetAttribute(mma_gemm_bt,
                         cudaFuncAttributeMaxDynamicSharedMemorySize, GSMEM);
    cudaFuncSetAttribute(flash_mma_kernel,
                         cudaFuncAttributeMaxDynamicSharedMemorySize,
                         FLASH_SMEM);

    const int nA4 = MROWS * DMODEL / 4;   // 1048576
    const int nW4 = DMODEL * DMODEL / 4;  // 262144
    dim3 ggrid(DMODEL / 128, MROWS / 128);  // (8, 32)

    // Q projection -> bf16 split, scaled by 0.125*log2(e)
    cvt_split4_kernel<<<nA4 / 256, 256>>>((const float4*)q, (uint2*)ah, (uint2*)al, nA4);
    cvt_split4_kernel<<<nW4 / 256, 256>>>((const float4*)w_q, (uint2*)wh, (uint2*)wl, nW4);
    mma_gemm_bt<<<ggrid, 256, GSMEM>>>(ah, al, wh, wl, nullptr, qh, ql, QSCALE);
    // K projection -> bf16 split
    cvt_split4_kernel<<<nA4 / 256, 256>>>((const float4*)k, (uint2*)ah, (uint2*)al, nA4);
    cvt_split4_kernel<<<nW4 / 256, 256>>>((const float4*)w_k, (uint2*)wh, (uint2*)wl, nW4);
    mma_gemm_bt<<<ggrid, 256, GSMEM>>>(ah, al, wh, wl, nullptr, kh, kl, 1.0f);
    // V projection -> bf16 split
    cvt_split4_kernel<<<nA4 / 256, 256>>>((const float4*)v, (uint2*)ah, (uint2*)al, nA4);
    cvt_split4_kernel<<<nW4 / 256, 256>>>((const float4*)w_v, (uint2*)wh, (uint2*)wl, nW4);
    mma_gemm_bt<<<ggrid, 256, GSMEM>>>(ah, al, wh, wl, nullptr, vh, vl, 1.0f);

    // Flash attention (writes bf16 split output directly into ah/al)
    dim3 agrid(SEQ / 128, NHEAD, BATCH);  // (16, 16, 2)
    flash_mma_kernel<<<agrid, 256, FLASH_SMEM>>>(qh, ql, kh, kl, vh, vl, ah, al);

    // Output projection -> fp32 out
    cvt_split4_kernel<<<nW4 / 256, 256>>>((const float4*)w_o, (uint2*)wh, (uint2*)wl, nW4);
    mma_gemm_bt<<<ggrid, 256, GSMEM>>>(ah, al, wh, wl, out, nullptr, nullptr, 1.0f);
}